// round 10
// baseline (speedup 1.0000x reference)
#include <cuda_runtime.h>
#include <cstdint>

#define NU 400000
#define NN 600000
#define MAXNNZ 1200000
#define DV 16              // float4 words per row (D=64)
#define BATCH 8192
#define SEC (BATCH * DV)

#define SCAN_TPB 256
#define SCAN_ITEMS 4
#define SCAN_CHUNK 1024
#define NB_SCAN ((NN + SCAN_CHUNK - 1) / SCAN_CHUNK)   // 586

// ---- scratch (device globals; allocation is forbidden) ----
__device__ int2  g_scsr[MAXNNZ];           // packed {col, val}
__device__ int2  g_rowdesc[NN];            // {start, deg}
__device__ int   g_wpos[NN];               // absolute write cursors
__device__ int   g_sizes[NN];              // per-row embedding size (prefix-mask sum)
// single-memset blob (ints): [0,NN)=deg | [NN,NN+NB_SCAN)=scan state | rest = flag bytes
#define FLAG_OFF (NN + NB_SCAN)
#define BLOB_INTS (NN + NB_SCAN + NN / 4)
__device__ int   g_blob[BLOB_INTS];

// ================= per-row sizes from prefix masks (streaming, overlapped) =================
__global__ void sizes_k(const int4* __restrict__ um, const int4* __restrict__ im,
                        int* __restrict__ sizes) {
    int t = blockIdx.x * blockDim.x + threadIdx.x;
    if (t >= NN * DV) return;
    int r = t >> 4, lane = t & 15;
    int4 m = (r < NU) ? __ldg(um + r * DV + lane) : __ldg(im + (r - NU) * DV + lane);
    int s = m.x + m.y + m.z + m.w;
    s += __shfl_down_sync(0xffffffffu, s, 8, 16);
    s += __shfl_down_sync(0xffffffffu, s, 4, 16);
    s += __shfl_down_sync(0xffffffffu, s, 2, 16);
    s += __shfl_down_sync(0xffffffffu, s, 1, 16);
    if (lane == 0) sizes[r] = s;
}

// ================= CSR build =================
__global__ void hist_k(const int4* __restrict__ r4, const int4* __restrict__ c4,
                       int* __restrict__ deg,
                       int n4, const int* __restrict__ r, const int* __restrict__ c, int E) {
    int i = blockIdx.x * blockDim.x + threadIdx.x;
    if (i < n4) {
        int4 rr = __ldg(r4 + i);
        int4 cc = __ldg(c4 + i);
        atomicAdd(&deg[rr.x], 1); atomicAdd(&deg[cc.x], 1);
        atomicAdd(&deg[rr.y], 1); atomicAdd(&deg[cc.y], 1);
        atomicAdd(&deg[rr.z], 1); atomicAdd(&deg[cc.z], 1);
        atomicAdd(&deg[rr.w], 1); atomicAdd(&deg[cc.w], 1);
    } else if (i == n4) {
        for (int j = n4 * 4; j < E; j++) { atomicAdd(&deg[r[j]], 1); atomicAdd(&deg[c[j]], 1); }
    }
}

// Single-pass decoupled-lookback scan: deg -> wpos (cursors) + rowdesc {start,deg}
__global__ void scan_k(const int* __restrict__ deg, int* __restrict__ wpos,
                       int2* __restrict__ rowdesc, unsigned int* state) {
    __shared__ int sh[SCAN_TPB];
    __shared__ int sbase;
    int bid = blockIdx.x;
    int base = bid * SCAN_CHUNK + threadIdx.x * SCAN_ITEMS;
    int v[SCAN_ITEMS]; int s = 0;
#pragma unroll
    for (int k = 0; k < SCAN_ITEMS; k++) {
        int idx = base + k;
        v[k] = (idx < NN) ? deg[idx] : 0;
        s += v[k];
    }
    sh[threadIdx.x] = s; __syncthreads();
    for (int off = 1; off < SCAN_TPB; off <<= 1) {
        int t = (threadIdx.x >= off) ? sh[threadIdx.x - off] : 0;
        __syncthreads();
        sh[threadIdx.x] += t;
        __syncthreads();
    }
    if (threadIdx.x == 0) {
        unsigned int total = (unsigned int)sh[SCAN_TPB - 1];
        if (bid == 0) {
            atomicExch(&state[0], (2u << 30) | total);
            sbase = 0;
        } else {
            atomicExch(&state[bid], (1u << 30) | total);
            unsigned int excl = 0;
            int j = bid - 1;
            while (true) {
                unsigned int st;
                do { st = atomicAdd(&state[j], 0u); } while ((st >> 30) == 0u);
                excl += st & 0x3FFFFFFFu;
                if ((st >> 30) == 2u) break;
                j--;
            }
            atomicExch(&state[bid], (2u << 30) | (excl + total));
            sbase = (int)excl;
        }
    }
    __syncthreads();
    int run = sbase + (sh[threadIdx.x] - s);
#pragma unroll
    for (int k = 0; k < SCAN_ITEMS; k++) {
        int idx = base + k;
        if (idx < NN) { wpos[idx] = run; rowdesc[idx] = make_int2(run, v[k]); }
        run += v[k];
    }
}

// Frontier-filtered symmetric scatter: insert only for endpoints in the dist<=2 closure.
__global__ void scatter_k(const int4* __restrict__ r4, const int4* __restrict__ c4,
                          const float4* __restrict__ v4,
                          const unsigned char* __restrict__ fb,
                          int* __restrict__ wpos, int2* __restrict__ csr,
                          int n4, const int* __restrict__ r, const int* __restrict__ c,
                          const float* __restrict__ v, int E) {
    int i = blockIdx.x * blockDim.x + threadIdx.x;
    if (i < n4) {
        int4 rr = __ldg(r4 + i);
        int4 cc = __ldg(c4 + i);
        float4 vv = __ldg(v4 + i);
        unsigned char fr0 = fb[rr.x], fc0 = fb[cc.x];
        unsigned char fr1 = fb[rr.y], fc1 = fb[cc.y];
        unsigned char fr2 = fb[rr.z], fc2 = fb[cc.z];
        unsigned char fr3 = fb[rr.w], fc3 = fb[cc.w];
        if (fr0) { int p = atomicAdd(&wpos[rr.x], 1); csr[p] = make_int2(cc.x, __float_as_int(vv.x)); }
        if (fc0) { int p = atomicAdd(&wpos[cc.x], 1); csr[p] = make_int2(rr.x, __float_as_int(vv.x)); }
        if (fr1) { int p = atomicAdd(&wpos[rr.y], 1); csr[p] = make_int2(cc.y, __float_as_int(vv.y)); }
        if (fc1) { int p = atomicAdd(&wpos[cc.y], 1); csr[p] = make_int2(rr.y, __float_as_int(vv.y)); }
        if (fr2) { int p = atomicAdd(&wpos[rr.z], 1); csr[p] = make_int2(cc.z, __float_as_int(vv.z)); }
        if (fc2) { int p = atomicAdd(&wpos[cc.z], 1); csr[p] = make_int2(rr.z, __float_as_int(vv.z)); }
        if (fr3) { int p = atomicAdd(&wpos[rr.w], 1); csr[p] = make_int2(cc.w, __float_as_int(vv.w)); }
        if (fc3) { int p = atomicAdd(&wpos[cc.w], 1); csr[p] = make_int2(rr.w, __float_as_int(vv.w)); }
    } else if (i == n4) {
        for (int j = n4 * 4; j < E; j++) {
            int rj = r[j], cj = c[j]; float vj = v[j];
            if (fb[rj]) { int p = atomicAdd(&wpos[rj], 1); csr[p] = make_int2(cj, __float_as_int(vj)); }
            if (fb[cj]) { int p = atomicAdd(&wpos[cj], 1); csr[p] = make_int2(rj, __float_as_int(vj)); }
        }
    }
}

// ============ seed flags + init output (ILP-2) ============
__global__ void seed_init_k(const float4* __restrict__ ue, const float4* __restrict__ ie,
                            const int4* __restrict__ um, const int4* __restrict__ im,
                            const int* __restrict__ users, const int* __restrict__ pos,
                            const int* __restrict__ neg,
                            unsigned char* __restrict__ fb, float4* __restrict__ out) {
    const int HALF = 3 * SEC / 2;
    int t = blockIdx.x * blockDim.x + threadIdx.x;
    if (t >= HALF) return;
#pragma unroll
    for (int u = 0; u < 2; u++) {
        int i = t + u * HALF;
        int sec = i / SEC;
        int rem = i - sec * SEC;
        int b = rem >> 4, lane = rem & 15;
        int row = (sec == 0) ? users[b] : (sec == 1 ? NU + pos[b] : NU + neg[b]);
        float4 e; int4 m;
        if (row < NU) { e = ue[row * DV + lane]; m = um[row * DV + lane]; }
        else          { int j = (row - NU) * DV + lane; e = ie[j]; m = im[j]; }
        float4 v;
        v.x = m.x ? e.x : 0.f;
        v.y = m.y ? e.y : 0.f;
        v.z = m.z ? e.z : 0.f;
        v.w = m.w ? e.w : 0.f;
        out[i] = v;
        out[3 * SEC + i] = v;
        if (lane == 0) fb[row] = 1;
    }
}

// ============ frontier pass (symmetric, in-place single flag, ILP-4) ============
__global__ void fpass_k(const int4* __restrict__ r4, const int4* __restrict__ c4,
                        unsigned char* __restrict__ fb,
                        int n4, const int* __restrict__ r, const int* __restrict__ c, int E) {
    int i = blockIdx.x * blockDim.x + threadIdx.x;
    if (i < n4) {
        int4 rr = __ldg(r4 + i);
        int4 cc = __ldg(c4 + i);
        bool r0 = fb[rr.x], r1 = fb[rr.y], r2 = fb[rr.z], r3 = fb[rr.w];
        bool c0 = fb[cc.x], c1 = fb[cc.y], c2 = fb[cc.z], c3 = fb[cc.w];
        if (r0) fb[cc.x] = 1;
        if (r1) fb[cc.y] = 1;
        if (r2) fb[cc.z] = 1;
        if (r3) fb[cc.w] = 1;
        if (c0) fb[rr.x] = 1;
        if (c1) fb[rr.y] = 1;
        if (c2) fb[rr.z] = 1;
        if (c3) fb[rr.w] = 1;
    } else if (i == n4) {
        for (int j = n4 * 4; j < E; j++) {
            if (fb[r[j]]) fb[c[j]] = 1;
            if (fb[c[j]]) fb[r[j]] = 1;
        }
    }
}

// ============ masked x0 gather helper ============
__device__ __forceinline__ float4 gx(int n, int lane, int k,
                                     const float4* __restrict__ ue,
                                     const float4* __restrict__ ie,
                                     const int* __restrict__ sizes) {
    int idx = (n < NU) ? n * DV + lane : (n - NU) * DV + lane;
    float4 x = (n < NU) ? __ldg(ue + idx) : __ldg(ie + idx);
    int s = __ldg(sizes + n);
    float4 r;
    r.x = (k + 0 < s) ? x.x : 0.f;
    r.y = (k + 1 < s) ? x.y : 0.f;
    r.z = (k + 2 < s) ? x.z : 0.f;
    r.w = (k + 3 < s) ? x.w : 0.f;
    return r;
}

// ============ 3-hop tree-walk: out = (x0[r] + l1[r] + l2[r] + l3[r]) / 4 ============
__global__ void mega_k(const float4* __restrict__ ue, const float4* __restrict__ ie,
                       const int* __restrict__ sizes,
                       const int2* __restrict__ rowdesc, const int2* __restrict__ csr,
                       const int* __restrict__ users, const int* __restrict__ pos,
                       const int* __restrict__ neg, float4* __restrict__ out) {
    int i = blockIdx.x * blockDim.x + threadIdx.x;
    if (i >= 3 * SEC) return;
    int sec = i / SEC;
    int rem = i - sec * SEC;
    int b = rem >> 4, lane = rem & 15;
    int k = lane << 2;
    int row = (sec == 0) ? users[b] : (sec == 1 ? NU + pos[b] : NU + neg[b]);

    float4 acc = make_float4(0.f, 0.f, 0.f, 0.f);
    int2 rd = __ldg(rowdesc + row);
    for (int j1 = rd.x; j1 < rd.x + rd.y; j1++) {
        int2 q1 = __ldg(csr + j1);
        int n1 = q1.x;
        float v1 = __int_as_float(q1.y);
        float4 x1 = gx(n1, lane, k, ue, ie, sizes);
        acc.x += v1 * x1.x;
        acc.y += v1 * x1.y;
        acc.z += v1 * x1.z;
        acc.w += v1 * x1.w;
        int2 rd1 = __ldg(rowdesc + n1);
        for (int j2 = rd1.x; j2 < rd1.x + rd1.y; j2++) {
            int2 q2 = __ldg(csr + j2);
            int n2 = q2.x;
            float w2 = v1 * __int_as_float(q2.y);
            float4 x2 = gx(n2, lane, k, ue, ie, sizes);
            acc.x += w2 * x2.x;
            acc.y += w2 * x2.y;
            acc.z += w2 * x2.z;
            acc.w += w2 * x2.w;
            int2 rd2 = __ldg(rowdesc + n2);
            for (int j3 = rd2.x; j3 < rd2.x + rd2.y; j3++) {
                int2 q3 = __ldg(csr + j3);
                float w3 = w2 * __int_as_float(q3.y);
                float4 x3 = gx(q3.x, lane, k, ue, ie, sizes);
                acc.x += w3 * x3.x;
                acc.y += w3 * x3.y;
                acc.z += w3 * x3.z;
                acc.w += w3 * x3.w;
            }
        }
    }
    float4 a = out[i];
    float4 r;
    r.x = (a.x + acc.x) * 0.25f;
    r.y = (a.y + acc.y) * 0.25f;
    r.z = (a.z + acc.z) * 0.25f;
    r.w = (a.w + acc.w) * 0.25f;
    out[i] = r;
}

extern "C" void kernel_launch(void* const* d_in, const int* in_sizes, int n_in,
                              void* d_out, int out_size) {
    const float* ue   = (const float*)d_in[0];
    const float* ie   = (const float*)d_in[1];
    const int*   um   = (const int*)  d_in[2];
    const int*   im   = (const int*)  d_in[3];
    const int*   rows = (const int*)  d_in[4];
    const int*   cols = (const int*)  d_in[5];
    const float* vals = (const float*)d_in[6];
    const int*   users= (const int*)  d_in[7];
    const int*   pos  = (const int*)  d_in[8];
    const int*   neg  = (const int*)  d_in[9];
    int nnz = in_sizes[4];
    int E = nnz / 2;          // COO is mirrored [u->it ; it->u]
    float* out = (float*)d_out;

    int2 *csr, *rowdesc;
    int *wpos, *sizes, *blob;
    cudaGetSymbolAddress((void**)&csr, g_scsr);
    cudaGetSymbolAddress((void**)&rowdesc, g_rowdesc);
    cudaGetSymbolAddress((void**)&wpos, g_wpos);
    cudaGetSymbolAddress((void**)&sizes, g_sizes);
    cudaGetSymbolAddress((void**)&blob, g_blob);

    int* deg = blob;
    unsigned int* state = (unsigned int*)(blob + NN);
    unsigned char* fb = (unsigned char*)(blob + FLAG_OFF);

    // lazily-created aux streams + events (host-side handles only)
    static cudaStream_t s1 = nullptr, s2 = nullptr;
    static cudaEvent_t evFork = nullptr, evClr = nullptr, evFlags = nullptr, evSizes = nullptr;
    if (s1 == nullptr) {
        cudaStreamCreateWithFlags(&s1, cudaStreamNonBlocking);
        cudaStreamCreateWithFlags(&s2, cudaStreamNonBlocking);
        cudaEventCreateWithFlags(&evFork, cudaEventDisableTiming);
        cudaEventCreateWithFlags(&evClr, cudaEventDisableTiming);
        cudaEventCreateWithFlags(&evFlags, cudaEventDisableTiming);
        cudaEventCreateWithFlags(&evSizes, cudaEventDisableTiming);
    }

    const int TPB = 256;
    const int n4 = E / 4;
    const int e4Blocks = (n4 + 1 + TPB - 1) / TPB;
    const int szBlocks = (NN * DV + TPB - 1) / TPB;
    const int seedBlocks = (3 * SEC / 2 + TPB - 1) / TPB;
    const int megaBlocks = (3 * SEC + TPB - 1) / TPB;

    // legal capture fork: record on origin stream first, side streams wait
    cudaEventRecord(evFork, 0);
    cudaStreamWaitEvent(s1, evFork, 0);
    cudaStreamWaitEvent(s2, evFork, 0);

    // chain C (s2): per-row sizes — independent, streaming, fully overlapped
    sizes_k<<<szBlocks, TPB, 0, s2>>>((const int4*)um, (const int4*)im, sizes);
    cudaEventRecord(evSizes, s2);

    // ---- chain A (default): memset (deg+state+flags) -> hist -> scan ----
    cudaMemsetAsync(blob, 0, BLOB_INTS * sizeof(int));
    cudaEventRecord(evClr, 0);
    hist_k<<<e4Blocks, TPB>>>((const int4*)rows, (const int4*)cols, deg,
                              n4, rows, cols, E);
    scan_k<<<NB_SCAN, SCAN_TPB>>>(deg, wpos, rowdesc, state);

    // ---- chain B (s1): seed (after flag clear!) + 2 in-place frontier passes ----
    cudaStreamWaitEvent(s1, evClr, 0);
    seed_init_k<<<seedBlocks, TPB, 0, s1>>>((const float4*)ue, (const float4*)ie,
                                            (const int4*)um, (const int4*)im,
                                            users, pos, neg, fb, (float4*)out);
    fpass_k<<<e4Blocks, TPB, 0, s1>>>((const int4*)rows, (const int4*)cols, fb,
                                      n4, rows, cols, E);
    fpass_k<<<e4Blocks, TPB, 0, s1>>>((const int4*)rows, (const int4*)cols, fb,
                                      n4, rows, cols, E);
    cudaEventRecord(evFlags, s1);

    // scatter needs flags + scan cursors
    cudaStreamWaitEvent(0, evFlags, 0);
    scatter_k<<<e4Blocks, TPB>>>((const int4*)rows, (const int4*)cols, (const float4*)vals,
                                 fb, wpos, csr, n4, rows, cols, vals, E);

    // mega needs scatter (in-stream) + sizes
    cudaStreamWaitEvent(0, evSizes, 0);
    mega_k<<<megaBlocks, TPB>>>((const float4*)ue, (const float4*)ie, sizes,
                                rowdesc, csr, users, pos, neg, (float4*)out);
}